// round 3
// baseline (speedup 1.0000x reference)
#include <cuda_runtime.h>

// VelocityLoss on GB300 — smem-staged version.
// Algebraic reductions (verified R1/R2): _train_x1/_train_x2 unused; mean_p
// cancels in the velocity diff; W_MAT is a fixed sparse joint->part scatter.
//
// Block = 640 threads (20 warps) stages 81 rows (80 + prev) of one batch into
// smem with coalesced float4 loads, then each warp computes 4 rows with the
// lane-per-joint pattern (lanes 0..23, part groups shuffle-aligned so 3
// shuffles produce all 5 part sums). LDS pattern is bank-conflict-free.

namespace {
constexpr int B_   = 512;
constexpr int S_   = 480;
constexpr int F_   = 149;
constexpr int VF_  = 5;
constexpr int TILE = 80;                 // rows per block
constexpr int WARPS = 20;                // 4 rows per warp
constexpr int THREADS = WARPS * 32;      // 640
constexpr int TPB_ = S_ / TILE;          // 6 tiles per batch
constexpr int NBLK = B_ * TPB_;          // 3072 blocks
constexpr int SMF = (TILE + 1) * F_ + 8; // smem floats (81 rows + align slack)
}

__device__ double g_acc[3] = {0.0, 0.0, 0.0};
__device__ unsigned int g_ticket = 0;

// lane -> joint, remapped so part groups are shuffle-aligned:
// lanes 0-7 part0, 8-11 part1, 12-15 part2, 16-19 part3, 20-23 part4
__constant__ int c_j[24] = {
    8, 9, 10, 11, 12, 21, 22, 23,
    0, 1, 2, 3,
    4, 5, 6, 7,
    13, 14, 15, 16,
    17, 18, 19, 20
};
__constant__ float c_wl[24] = {
    1.f/9, 1.f/9, 1.f/9, 1.f/9, 1.f/9, 1.f/9, 2.f/9, 1.f/9,
    0.1f, 0.2f, 0.3f, 0.4f,
    0.1f, 0.2f, 0.3f, 0.4f,
    0.1f, 0.2f, 0.3f, 0.4f,
    0.1f, 0.2f, 0.3f, 0.4f
};

__global__ void __launch_bounds__(THREADS, 2) vel_loss_staged(
    const float* __restrict__ pred,   // (B, S, F)
    const float* __restrict__ tvft,   // (B, S+1, VF)
    const float* __restrict__ meanv,  // (F,)
    const float* __restrict__ stdv,   // (F,)
    float* __restrict__ out)
{
    __shared__ __align__(16) float sm[SMF];
    __shared__ double sA[WARPS], sB[WARPS], sC[WARPS];

    const int tid  = threadIdx.x;
    const int lane = tid & 31;
    const int warp = tid >> 5;
    const int b    = blockIdx.x / TPB_;
    const int s0   = (blockIdx.x % TPB_) * TILE;

    // ---------------- stage 1: coalesced load into smem ----------------
    // smem row l <-> global row s = s0 - 1 + l  (l=0 garbage when s0==0)
    const int sOffRow  = (s0 > 0) ? 0 : 1;
    const int nRows    = (s0 > 0) ? (TILE + 1) : TILE;
    const size_t gbase = ((size_t)b * S_ + (s0 > 0 ? s0 - 1 : 0)) * F_;
    const int nFloats  = nRows * F_;
    const float* gp    = pred + gbase;

    const int head = (int)((4 - (gbase & 3)) & 3);          // floats to 16B boundary
    const int dlt  = (int)((-(sOffRow * F_ + head)) & 3);    // smem shift so vec region is 16B aligned
    float* sbase = sm + sOffRow * F_ + dlt;

    if (tid < head) sbase[tid] = gp[tid];
    const int n4 = (nFloats - head) >> 2;
    const float4* __restrict__ g4 = (const float4*)(gp + head);
    float4* s4 = (float4*)(sbase + head);
    for (int i = tid; i < n4; i += THREADS) s4[i] = g4[i];
    for (int i = head + (n4 << 2) + tid; i < nFloats; i += THREADS) sbase[i] = gp[i];

    // ---------------- per-lane constants (overlaps with loads) ----------------
    int jj = 0; float w = 0.f;
    float sp0 = 0, sp1 = 0, sp2 = 0, mv0 = 0, mv1 = 0, mv2 = 0, rv0 = 0, rv1 = 0, rv2 = 0;
    if (lane < 24) {
        jj = c_j[lane] * 3;
        w  = c_wl[lane];
        sp0 = stdv[jj];       sp1 = stdv[jj + 1];     sp2 = stdv[jj + 2];
        mv0 = meanv[72 + jj]; mv1 = meanv[72 + jj + 1]; mv2 = meanv[72 + jj + 2];
        rv0 = 1.0f / stdv[72 + jj];
        rv1 = 1.0f / stdv[72 + jj + 1];
        rv2 = 1.0f / stdv[72 + jj + 2];
    }
    int pidx = -1;
    if      (lane == 0)  pidx = 0;
    else if (lane == 8)  pidx = 1;
    else if (lane == 12) pidx = 2;
    else if (lane == 16) pidx = 3;
    else if (lane == 20) pidx = 4;
    float mf = 0.f, rf = 0.f;
    if (pidx >= 0) { mf = meanv[144 + pidx]; rf = 1.0f / stdv[144 + pidx]; }

    __syncthreads();

    // ---------------- stage 2: compute 4 rows per warp ----------------
    const int sFirst = s0 + warp * 4;
    const float* smv = sm + dlt;          // row l starts at smv + l*F_
    const float* trbase = tvft + ((size_t)b * (S_ + 1)) * VF_;

    float accA = 0.f, accB = 0.f, accC = 0.f;
    float p0 = 0.f, p1 = 0.f, p2 = 0.f;

    // init prev positions
    if (sFirst == 0) {
        const float* r1 = smv + F_;       // row s=0 (l=1)
        if (lane < 24) {
            p0 = r1[jj]; p1 = r1[jj + 1]; p2 = r1[jj + 2];
            const float q0 = r1[77 + jj], q1 = r1[78 + jj], q2 = r1[79 + jj];
            accB = q0 * q0 + q1 * q1 + q2 * q2;
        }
    } else {
        const float* pr = smv + (size_t)(warp * 4) * F_;   // l = 4w <-> s = sFirst-1
        if (lane < 24) { p0 = pr[jj]; p1 = pr[jj + 1]; p2 = pr[jj + 2]; }
    }

    #pragma unroll
    for (int r = 0; r < 4; ++r) {
        const int s = sFirst + r;
        if (s == 0) continue;             // only warp0/r0 of the s0==0 tile
        const float* cr = smv + (size_t)(warp * 4 + r + 1) * F_;
        float contrib = 0.f;
        if (lane < 24) {
            const float c0 = cr[jj], c1 = cr[jj + 1], c2 = cr[jj + 2];
            const float q0 = cr[77 + jj], q1 = cr[78 + jj], q2 = cr[79 + jj];
            const float v0 = (c0 - p0) * sp0;
            const float v1 = (c1 - p1) * sp1;
            const float v2 = (c2 - p2) * sp2;
            const float d0 = q0 - (v0 - mv0) * rv0;
            const float d1 = q1 - (v1 - mv1) * rv1;
            const float d2 = q2 - (v2 - mv2) * rv2;
            accA += d0 * d0 + d1 * d1 + d2 * d2;
            contrib = sqrtf(v0 * v0 + v1 * v1 + v2 * v2) * w;
            p0 = c0; p1 = c1; p2 = c2;
        }
        float g4v = contrib;
        g4v += __shfl_xor_sync(0xffffffffu, g4v, 1);
        g4v += __shfl_xor_sync(0xffffffffu, g4v, 2);
        const float g8v = g4v + __shfl_xor_sync(0xffffffffu, g4v, 4);
        if (pidx >= 0) {
            const float f = (pidx == 0) ? g8v : g4v;
            const float d = trbase[(size_t)s * VF_ + pidx] - (f - mf) * rf;
            accC += d * d;
        }
    }

    // ---------------- reduction ----------------
    #pragma unroll
    for (int off = 16; off; off >>= 1) {
        accA += __shfl_xor_sync(0xffffffffu, accA, off);
        accB += __shfl_xor_sync(0xffffffffu, accB, off);
        accC += __shfl_xor_sync(0xffffffffu, accC, off);
    }
    if (lane == 0) {
        sA[warp] = (double)accA;
        sB[warp] = (double)accB;
        sC[warp] = (double)accC;
    }
    __syncthreads();

    if (warp == 0) {
        double a  = (lane < WARPS) ? sA[lane] : 0.0;
        double bb = (lane < WARPS) ? sB[lane] : 0.0;
        double c  = (lane < WARPS) ? sC[lane] : 0.0;
        #pragma unroll
        for (int off = 16; off; off >>= 1) {
            a  += __shfl_xor_sync(0xffffffffu, a, off);
            bb += __shfl_xor_sync(0xffffffffu, bb, off);
            c  += __shfl_xor_sync(0xffffffffu, c, off);
        }
        if (lane == 0) {
            atomicAdd(&g_acc[0], a);
            atomicAdd(&g_acc[1], bb);
            atomicAdd(&g_acc[2], c);
            __threadfence();
            const unsigned t = atomicAdd(&g_ticket, 1u);
            if (t == (unsigned)(NBLK - 1)) {
                __threadfence();
                volatile double* ga = g_acc;
                const double A  = ga[0];
                const double B0 = ga[1];
                const double C  = ga[2];
                const double nA = (double)B_ * (double)(S_ - 1) * 72.0;
                const double nB = (double)B_ * 72.0;
                const double nC = (double)B_ * (double)(S_ - 1) * (double)VF_;
                const double loss1 = 10.0 * A / nA + 20.0 * B0 / nB;
                const double loss2 = 10.0 * C / nC;
                out[0] = (float)(2.0 * loss1 + 1.5 * loss2);
                ga[0] = 0.0; ga[1] = 0.0; ga[2] = 0.0;
                g_ticket = 0;
            }
        }
    }
}

extern "C" void kernel_launch(void* const* d_in, const int* in_sizes, int n_in,
                              void* d_out, int out_size) {
    const float* pred = (const float*)d_in[0];   // predict_seq (B,S,F)
    // d_in[1] = _train_x1 (unused), d_in[2] = _train_x2 (unused)
    const float* tvft = (const float*)d_in[3];   // _true_vel_factor (B,S+1,VF)
    const float* mean = (const float*)d_in[4];   // _mean (F,)
    const float* stdv = (const float*)d_in[5];   // _std (F,)

    vel_loss_staged<<<NBLK, THREADS>>>(pred, tvft, mean, stdv, (float*)d_out);
}

// round 4
// speedup vs baseline: 1.7683x; 1.7683x over previous
#include <cuda_runtime.h>

// VelocityLoss on GB300 — direct-LDG (R2 structure) + 4-row batching for MLP
// and pipelined shuffle chains. R3's smem staging regressed (serialized
// phases, extra L1 traffic) and is abandoned.
//
// Layout: one warp owns CH=16 consecutive sequence rows of one batch.
// Lanes 0..23 each own one joint (3 floats); lane->joint remapped so the 5
// body parts are shuffle-aligned groups (xor 1,2 give 4-groups, +xor 4 gives
// the 8-group for part0). 3 shuffles/row, batched 4 rows at a time so the
// chains pipeline.

namespace {
constexpr int B_  = 512;
constexpr int S_  = 480;
constexpr int F_  = 149;
constexpr int VF_ = 5;
constexpr int CH  = 16;                   // rows per warp chunk
constexpr int CPB = S_ / CH;              // 30 chunks per batch row
constexpr int WPB = 8;                    // warps per block (256 threads)
constexpr int NBLK = B_ * CPB / WPB;      // 1920 blocks
}

__device__ double g_acc[3] = {0.0, 0.0, 0.0};
__device__ unsigned int g_ticket = 0;

// lane -> joint, part groups shuffle-aligned:
// lanes 0-7 part0, 8-11 part1, 12-15 part2, 16-19 part3, 20-23 part4
__constant__ int c_j[24] = {
    8, 9, 10, 11, 12, 21, 22, 23,
    0, 1, 2, 3,
    4, 5, 6, 7,
    13, 14, 15, 16,
    17, 18, 19, 20
};
__constant__ float c_wl[24] = {
    1.f/9, 1.f/9, 1.f/9, 1.f/9, 1.f/9, 1.f/9, 2.f/9, 1.f/9,
    0.1f, 0.2f, 0.3f, 0.4f,
    0.1f, 0.2f, 0.3f, 0.4f,
    0.1f, 0.2f, 0.3f, 0.4f,
    0.1f, 0.2f, 0.3f, 0.4f
};

__global__ void __launch_bounds__(256) vel_loss_batched(
    const float* __restrict__ pred,   // (B, S, F)
    const float* __restrict__ tvft,   // (B, S+1, VF)
    const float* __restrict__ meanv,  // (F,)
    const float* __restrict__ stdv,   // (F,)
    float* __restrict__ out)
{
    const int tid  = threadIdx.x;
    const int lane = tid & 31;
    const int warp = tid >> 5;
    const int idx  = blockIdx.x * WPB + warp;   // chunk id
    const int b    = idx / CPB;
    const int s0   = (idx % CPB) * CH;

    // per-lane joint parameters
    int jj = 0; float w = 0.f;
    float sp0 = 0, sp1 = 0, sp2 = 0, mv0 = 0, mv1 = 0, mv2 = 0, rv0 = 0, rv1 = 0, rv2 = 0;
    const bool act = (lane < 24);
    if (act) {
        jj = c_j[lane] * 3;
        w  = c_wl[lane];
        sp0 = stdv[jj];       sp1 = stdv[jj + 1];       sp2 = stdv[jj + 2];
        mv0 = meanv[72 + jj]; mv1 = meanv[72 + jj + 1]; mv2 = meanv[72 + jj + 2];
        rv0 = 1.0f / stdv[72 + jj];
        rv1 = 1.0f / stdv[72 + jj + 1];
        rv2 = 1.0f / stdv[72 + jj + 2];
    }
    int pidx = -1;
    if      (lane == 0)  pidx = 0;
    else if (lane == 8)  pidx = 1;
    else if (lane == 12) pidx = 2;
    else if (lane == 16) pidx = 3;
    else if (lane == 20) pidx = 4;
    float mf = 0.f, rf = 0.f;
    if (pidx >= 0) { mf = meanv[144 + pidx]; rf = 1.0f / stdv[144 + pidx]; }

    float accA = 0.f, accB = 0.f, accC = 0.f;

    const float* trbase = tvft + ((size_t)b * (S_ + 1)) * VF_;

    // prev-row positions in registers
    float p0 = 0.f, p1 = 0.f, p2 = 0.f;
    int sBeg = s0;
    {
        const float* r0 = pred + ((size_t)(b * S_ + s0)) * F_;
        if (s0 == 0) {
            if (act) {
                p0 = r0[jj]; p1 = r0[jj + 1]; p2 = r0[jj + 2];
                const float q0 = r0[77 + jj], q1 = r0[78 + jj], q2 = r0[79 + jj];
                accB = q0 * q0 + q1 * q1 + q2 * q2;   // s==0 zero-target term
            }
            sBeg = 1;
        } else if (act) {
            const float* rp = r0 - F_;
            p0 = rp[jj]; p1 = rp[jj + 1]; p2 = rp[jj + 2];
        }
    }

    const int sEnd = s0 + CH;
    int s = sBeg;

    // main loop: 4-row batches (aligned chunks get exactly 4 batches)
    for (; s + 4 <= sEnd; s += 4) {
        float c0[4], c1[4], c2[4], q0[4], q1[4], q2[4];
        const float* r = pred + ((size_t)(b * S_ + s)) * F_;
        // front-batched loads (high MLP)
        #pragma unroll
        for (int k = 0; k < 4; ++k) {
            const float* rr = r + (size_t)k * F_;
            if (act) {
                c0[k] = rr[jj];      c1[k] = rr[jj + 1];  c2[k] = rr[jj + 2];
                q0[k] = rr[77 + jj]; q1[k] = rr[78 + jj]; q2[k] = rr[79 + jj];
            }
        }
        float tr[4] = {0.f, 0.f, 0.f, 0.f};
        if (pidx >= 0) {
            #pragma unroll
            for (int k = 0; k < 4; ++k)
                tr[k] = trbase[(size_t)(s + k) * VF_ + pidx];
        }
        // compute per-row contributions (velocity chain is register-only)
        float contrib[4];
        #pragma unroll
        for (int k = 0; k < 4; ++k) {
            contrib[k] = 0.f;
            if (act) {
                const float v0 = (c0[k] - p0) * sp0;
                const float v1 = (c1[k] - p1) * sp1;
                const float v2 = (c2[k] - p2) * sp2;
                const float d0 = q0[k] - (v0 - mv0) * rv0;
                const float d1 = q1[k] - (v1 - mv1) * rv1;
                const float d2 = q2[k] - (v2 - mv2) * rv2;
                accA += d0 * d0 + d1 * d1 + d2 * d2;
                contrib[k] = sqrtf(v0 * v0 + v1 * v1 + v2 * v2) * w;
                p0 = c0[k]; p1 = c1[k]; p2 = c2[k];
            }
        }
        // 4 independent 3-deep shuffle chains (pipelined)
        float g4v[4], g8v[4];
        #pragma unroll
        for (int k = 0; k < 4; ++k) g4v[k] = contrib[k] + __shfl_xor_sync(0xffffffffu, contrib[k], 1);
        #pragma unroll
        for (int k = 0; k < 4; ++k) g4v[k] += __shfl_xor_sync(0xffffffffu, g4v[k], 2);
        #pragma unroll
        for (int k = 0; k < 4; ++k) g8v[k] = g4v[k] + __shfl_xor_sync(0xffffffffu, g4v[k], 4);
        if (pidx >= 0) {
            #pragma unroll
            for (int k = 0; k < 4; ++k) {
                const float f = (pidx == 0) ? g8v[k] : g4v[k];
                const float d = tr[k] - (f - mf) * rf;
                accC += d * d;
            }
        }
    }

    // tail (only the s0==0 chunk: 3 rows)
    for (; s < sEnd; ++s) {
        const float* r = pred + ((size_t)(b * S_ + s)) * F_;
        float contrib = 0.f;
        if (act) {
            const float cc0 = r[jj], cc1 = r[jj + 1], cc2 = r[jj + 2];
            const float qq0 = r[77 + jj], qq1 = r[78 + jj], qq2 = r[79 + jj];
            const float v0 = (cc0 - p0) * sp0;
            const float v1 = (cc1 - p1) * sp1;
            const float v2 = (cc2 - p2) * sp2;
            const float d0 = qq0 - (v0 - mv0) * rv0;
            const float d1 = qq1 - (v1 - mv1) * rv1;
            const float d2 = qq2 - (v2 - mv2) * rv2;
            accA += d0 * d0 + d1 * d1 + d2 * d2;
            contrib = sqrtf(v0 * v0 + v1 * v1 + v2 * v2) * w;
            p0 = cc0; p1 = cc1; p2 = cc2;
        }
        float g4v = contrib;
        g4v += __shfl_xor_sync(0xffffffffu, g4v, 1);
        g4v += __shfl_xor_sync(0xffffffffu, g4v, 2);
        const float g8v = g4v + __shfl_xor_sync(0xffffffffu, g4v, 4);
        if (pidx >= 0) {
            const float f = (pidx == 0) ? g8v : g4v;
            const float d = trbase[(size_t)s * VF_ + pidx] - (f - mf) * rf;
            accC += d * d;
        }
    }

    // warp reduction
    #pragma unroll
    for (int off = 16; off; off >>= 1) {
        accA += __shfl_xor_sync(0xffffffffu, accA, off);
        accB += __shfl_xor_sync(0xffffffffu, accB, off);
        accC += __shfl_xor_sync(0xffffffffu, accC, off);
    }

    __shared__ double sA[WPB], sB[WPB], sC[WPB];
    if (lane == 0) {
        sA[warp] = (double)accA;
        sB[warp] = (double)accB;
        sC[warp] = (double)accC;
    }
    __syncthreads();

    if (warp == 0) {
        double a  = (lane < WPB) ? sA[lane] : 0.0;
        double bb = (lane < WPB) ? sB[lane] : 0.0;
        double c  = (lane < WPB) ? sC[lane] : 0.0;
        #pragma unroll
        for (int off = 4; off; off >>= 1) {
            a  += __shfl_xor_sync(0xffffffffu, a, off);
            bb += __shfl_xor_sync(0xffffffffu, bb, off);
            c  += __shfl_xor_sync(0xffffffffu, c, off);
        }
        if (lane == 0) {
            atomicAdd(&g_acc[0], a);
            atomicAdd(&g_acc[1], bb);
            atomicAdd(&g_acc[2], c);
            __threadfence();
            const unsigned t = atomicAdd(&g_ticket, 1u);
            if (t == (unsigned)(NBLK - 1)) {
                __threadfence();
                volatile double* ga = g_acc;
                const double A  = ga[0];
                const double B0 = ga[1];
                const double C  = ga[2];
                const double nA = (double)B_ * (double)(S_ - 1) * 72.0;
                const double nB = (double)B_ * 72.0;
                const double nC = (double)B_ * (double)(S_ - 1) * (double)VF_;
                const double loss1 = 10.0 * A / nA + 20.0 * B0 / nB;
                const double loss2 = 10.0 * C / nC;
                out[0] = (float)(2.0 * loss1 + 1.5 * loss2);
                ga[0] = 0.0; ga[1] = 0.0; ga[2] = 0.0;
                g_ticket = 0;
            }
        }
    }
}

extern "C" void kernel_launch(void* const* d_in, const int* in_sizes, int n_in,
                              void* d_out, int out_size) {
    const float* pred = (const float*)d_in[0];   // predict_seq (B,S,F)
    // d_in[1] = _train_x1 (unused), d_in[2] = _train_x2 (unused)
    const float* tvft = (const float*)d_in[3];   // _true_vel_factor (B,S+1,VF)
    const float* mean = (const float*)d_in[4];   // _mean (F,)
    const float* stdv = (const float*)d_in[5];   // _std (F,)

    vel_loss_batched<<<NBLK, 256>>>(pred, tvft, mean, stdv, (float*)d_out);
}